// round 1
// baseline (speedup 1.0000x reference)
#include <cuda_runtime.h>

#define MODELS 8
#define BATCH 65536
#define CHOICE 100
#define WARPS_PER_BLOCK 8
#define NBLOCKS (BATCH / WARPS_PER_BLOCK)   // 8192

// scratch: per-block partial sums (no cudaMalloc allowed)
__device__ float g_partials[NBLOCKS];

__device__ __forceinline__ float warp_sum(float v) {
#pragma unroll
    for (int o = 16; o > 0; o >>= 1)
        v += __shfl_xor_sync(0xffffffffu, v, o);
    return v;
}

__global__ __launch_bounds__(256, 4) void mmnl_main(
    const float* __restrict__ x, const float* __restrict__ y,
    const float* __restrict__ z, const float* __restrict__ alpha,
    const float* __restrict__ u_prev, const float* __restrict__ u)
{
    __shared__ float s_alpha[MODELS];
    __shared__ float s_eup[MODELS];
    __shared__ float s_eu;
    __shared__ float s_t[WARPS_PER_BLOCK];

    const int tid = threadIdx.x;
    if (tid < MODELS) {
        s_alpha[tid] = alpha[tid];
        s_eup[tid]   = __expf(u_prev[tid]);
    }
    if (tid == 0) s_eu = __expf(u[0]);
    __syncthreads();

    const int lane = tid & 31;
    const int warp = tid >> 5;
    const int b    = blockIdx.x * WARPS_PER_BLOCK + warp;   // < BATCH always
    const size_t rowoff = (size_t)b * CHOICE;

    // ---- per-lane partials over the C=100 row (25 float4 per row) ----
    float4 yv = make_float4(0.f, 0.f, 0.f, 0.f);
    float sy = 0.f, xy = 0.f, sex = 0.f;
    if (lane < 25) {
        yv = __ldcs((const float4*)(y + rowoff) + lane);
        float4 xv = __ldcs((const float4*)(x + rowoff) + lane);
        sy  = yv.x + yv.y + yv.z + yv.w;
        xy  = xv.x * yv.x + xv.y * yv.y + xv.z * yv.z + xv.w * yv.w;
        sex = __expf(xv.x) + __expf(xv.y) + __expf(xv.z) + __expf(xv.w);
    }

    float zyp[MODELS], sep[MODELS];
#pragma unroll
    for (int m = 0; m < MODELS; m++) {
        zyp[m] = 0.f;
        sep[m] = 0.f;
        if (lane < 25) {
            float4 zv = __ldcs(
                (const float4*)(z + (size_t)m * BATCH * CHOICE + rowoff) + lane);
            zyp[m] = zv.x * yv.x + zv.y * yv.y + zv.z * yv.z + zv.w * yv.w;
            sep[m] = __expf(zv.x) + __expf(zv.y) + __expf(zv.z) + __expf(zv.w);
        }
    }

    // ---- warp reductions (butterfly -> all lanes hold full sums) ----
    sy  = warp_sum(sy);
    xy  = warp_sum(xy);
    sex = warp_sum(sex);
#pragma unroll
    for (int m = 0; m < MODELS; m++) {
        zyp[m] = warp_sum(zyp[m]);
        sep[m] = warp_sum(sep[m]);
    }

    // ---- per-customer scalar math ----
    const bool has = (sy > 0.5f);   // y is one-hot or all-zero
    float g = 0.f;
#pragma unroll
    for (int m = 0; m < MODELS; m++) {
        float eup   = s_eup[m];
        float num   = has ? __expf(zyp[m]) : eup;
        float denom = eup + sep[m];
        g += s_alpha[m] * num / denom;
    }
    float numx = has ? __expf(xy) : s_eu;
    float t = numx / ((s_eu + sex) * g);

    if (lane == 0) s_t[warp] = t;
    __syncthreads();

    if (tid == 0) {
        float acc = 0.f;
#pragma unroll
        for (int w = 0; w < WARPS_PER_BLOCK; w++) acc += s_t[w];
        g_partials[blockIdx.x] = acc;
    }
}

__global__ __launch_bounds__(256) void mmnl_reduce(float* __restrict__ out)
{
    __shared__ float sh[256];
    const int tid = threadIdx.x;
    float acc = 0.f;
    // fixed-order strided accumulation -> deterministic
    for (int i = tid; i < NBLOCKS; i += 256) acc += g_partials[i];
    sh[tid] = acc;
    __syncthreads();
#pragma unroll
    for (int s = 128; s > 0; s >>= 1) {
        if (tid < s) sh[tid] += sh[tid + s];
        __syncthreads();
    }
    if (tid == 0) out[0] = -sh[0] / (float)BATCH;
}

extern "C" void kernel_launch(void* const* d_in, const int* in_sizes, int n_in,
                              void* d_out, int out_size)
{
    const float* x      = (const float*)d_in[0];
    const float* y      = (const float*)d_in[1];
    const float* z      = (const float*)d_in[2];
    const float* alpha  = (const float*)d_in[3];
    const float* u_prev = (const float*)d_in[4];
    const float* u      = (const float*)d_in[5];
    float* out = (float*)d_out;

    mmnl_main<<<NBLOCKS, 256>>>(x, y, z, alpha, u_prev, u);
    mmnl_reduce<<<1, 256>>>(out);
}